// round 1
// baseline (speedup 1.0000x reference)
#include <cuda_runtime.h>

// Problem dims
#define TS   512      // timesteps
#define BBATCH 64     // batch
#define ID   512      // input dim
#define HD   512      // hidden dim
#define GD   2048     // 4*H packed gates

// Scan kernel config
#define NBLK 128          // persistent blocks (<=148 SMs, all co-resident)
#define HB   4            // hidden columns per block = HD/NBLK
#define HS_STRIDE 68      // padded row stride for h in smem (mult of 4, avoids conflicts)
#define US_FLOATS (ID * 16)            // U tile: [512][16] (hl-major, gate inner)
#define HS_FLOATS (ID * HS_STRIDE)     // h tile: [512][68]
#define SCAN_SMEM ((US_FLOATS + HS_FLOATS) * 4)

// Scratch (static device memory — no allocation in kernel_launch)
__device__ float g_xw[TS * BBATCH * GD];   // remapped: [t][hc][gate][b]
__device__ float g_h[2][HD * BBATCH];      // k-major: [hc][b], double-buffered
__device__ unsigned g_gen = 0;
__device__ unsigned g_count = 0;

// ---------------------------------------------------------------------------
// Kernel 1: xW = x @ W + b, written into remapped layout [t][hc][gate][b]
// Classic 128x128x8 SIMT SGEMM, 256 threads, 8x8 register tile.
// ---------------------------------------------------------------------------
__global__ void __launch_bounds__(256) gemm_xw_kernel(
    const float* __restrict__ A,     // x as [32768][512]
    const float* __restrict__ Bw,    // W as [512][2048]
    const float* __restrict__ bias)  // [2048]
{
    __shared__ float As[8][128];   // transposed A tile: As[k][m]
    __shared__ float Bs[8][128];   // Bs[k][n]

    const int tid = threadIdx.x;
    const int m0 = blockIdx.y * 128;
    const int n0 = blockIdx.x * 128;

    const int a_row = tid >> 1;          // 0..127
    const int a_col = (tid & 1) * 4;     // 0 or 4
    const int b_row = tid >> 5;          // 0..7
    const int b_col = (tid & 31) * 4;    // 0..124
    const int tx = (tid & 15) * 8;       // output col group
    const int ty = (tid >> 4) * 8;       // output row group

    float acc[8][8];
#pragma unroll
    for (int i = 0; i < 8; i++)
#pragma unroll
        for (int j = 0; j < 8; j++) acc[i][j] = 0.f;

    const float* Aptr = A + (m0 + a_row) * ID + a_col;
    const float* Bptr = Bw + b_row * GD + n0 + b_col;

    for (int k0 = 0; k0 < ID; k0 += 8) {
        float4 av = *(const float4*)(Aptr + k0);
        float4 bv = *(const float4*)(Bptr + (size_t)k0 * GD);
        __syncthreads();   // protect smem from previous iteration's readers
        As[a_col + 0][a_row] = av.x;
        As[a_col + 1][a_row] = av.y;
        As[a_col + 2][a_row] = av.z;
        As[a_col + 3][a_row] = av.w;
        *(float4*)&Bs[b_row][b_col] = bv;
        __syncthreads();
#pragma unroll
        for (int k = 0; k < 8; k++) {
            float af[8], bf[8];
            *(float4*)&af[0] = *(const float4*)&As[k][ty];
            *(float4*)&af[4] = *(const float4*)&As[k][ty + 4];
            *(float4*)&bf[0] = *(const float4*)&Bs[k][tx];
            *(float4*)&bf[4] = *(const float4*)&Bs[k][tx + 4];
#pragma unroll
            for (int i = 0; i < 8; i++)
#pragma unroll
                for (int j = 0; j < 8; j++)
                    acc[i][j] = fmaf(af[i], bf[j], acc[i][j]);
        }
    }

    // bias (8 consecutive columns per thread)
    float bvals[8];
    *(float4*)&bvals[0] = *(const float4*)&bias[n0 + tx];
    *(float4*)&bvals[4] = *(const float4*)&bias[n0 + tx + 4];

    // Remapped store: out[t*131072 + hc*256 + gate*64 + b]
#pragma unroll
    for (int i = 0; i < 8; i++) {
        int m = m0 + ty + i;
        int t = m >> 6;
        int b = m & 63;
        float* orow = g_xw + (size_t)t * (BBATCH * GD) + b;
#pragma unroll
        for (int j = 0; j < 8; j++) {
            int n = n0 + tx + j;
            int gate = n >> 9;
            int hc = n & 511;
            orow[hc * 256 + gate * 64] = acc[i][j] + bvals[j];
        }
    }
}

// ---------------------------------------------------------------------------
// Software grid barrier (sense via monotonic generation counter).
// Self-cleaning across graph replays (count always returns to 0).
// ---------------------------------------------------------------------------
__device__ __forceinline__ void grid_barrier_128()
{
    __syncthreads();
    if (threadIdx.x == 0) {
        __threadfence();                         // release my h writes
        volatile unsigned* vgen = &g_gen;
        unsigned gen = *vgen;
        if (atomicAdd(&g_count, 1) == NBLK - 1) {
            atomicExch(&g_count, 0);
            __threadfence();
            atomicAdd(&g_gen, 1);                // release all
        } else {
            while (*vgen == gen) { }
        }
        __threadfence();                         // acquire others' h writes
    }
    __syncthreads();
}

// ---------------------------------------------------------------------------
// Kernel 2: persistent LSTM scan.
// Block bid owns hidden cols [bid*4, bid*4+4). U tile stays in smem all steps.
// Per step: stage full h (k-major) into smem, g = xw_t + h@U, gate combine,
// write new h (double buffer) + output, grid barrier.
// ---------------------------------------------------------------------------
__global__ void __launch_bounds__(256) lstm_scan_kernel(
    const float* __restrict__ a0,   // [64][512]  (b-major)
    const float* __restrict__ U,    // [512][2048]
    float* __restrict__ out)        // [512][64][512]
{
    extern __shared__ float sm[];
    float* Us = sm;                  // [512][16] : k*16 + hl*4 + gate
    float* hs = sm + US_FLOATS;      // [512][68] : k*68 + b

    const int tid = threadIdx.x;
    const int bid = blockIdx.x;

    // Load U tile once (resident for all 512 steps)
    for (int i = tid; i < US_FLOATS; i += 256) {
        int k = i >> 4;
        int c = i & 15;
        int hl = c >> 2;
        int gate = c & 3;
        Us[i] = U[(size_t)k * GD + gate * HD + bid * HB + hl];
    }

    const int b  = tid & 63;
    const int hl = tid >> 6;                 // 0..3
    const int hc = bid * HB + hl;            // global hidden col
    const float* xwp = g_xw + hc * 256 + b;  // + t*131072 + gate*64
    const float* Up  = Us + hl * 4;

    for (int t = 0; t < TS; t++) {
        __syncthreads();   // all threads done reading hs from previous step
        if (t == 0) {
            // a0 is b-major [b][k] -> transpose into hs[k][b] (one-time slow path)
            for (int f = tid; f < BBATCH * HD; f += 256) {
                int bb = f >> 9;
                int kk = f & 511;
                hs[kk * HS_STRIDE + bb] = a0[f];
            }
        } else {
            // g_h is k-major: straight float4 copy with row padding
            const float* hsrc = g_h[(t ^ 1) & 1];
#pragma unroll
            for (int i = 0; i < 32; i++) {
                int f = i * 1024 + tid * 4;
                float4 v = *(const float4*)(hsrc + f);
                int kk = f >> 6;
                int bb = f & 63;
                *(float4*)&hs[kk * HS_STRIDE + bb] = v;
            }
        }
        __syncthreads();

        const float* xwt = xwp + (size_t)t * (BBATCH * GD);
        float acc0 = xwt[0];
        float acc1 = xwt[64];
        float acc2 = xwt[128];
        float acc3 = xwt[192];

#pragma unroll 8
        for (int k = 0; k < ID; k++) {
            float hv = hs[k * HS_STRIDE + b];
            float4 u = *(const float4*)(Up + k * 16);
            acc0 = fmaf(hv, u.x, acc0);
            acc1 = fmaf(hv, u.y, acc1);
            acc2 = fmaf(hv, u.z, acc2);
            acc3 = fmaf(hv, u.w, acc3);
        }

        float gu = 1.f / (1.f + __expf(-acc0));
        float gf = 1.f / (1.f + __expf(-acc1));
        float go = 1.f / (1.f + __expf(-acc2));
        float cd = tanhf(acc3);
        float hprev = hs[hc * HS_STRIDE + b];
        float cv = gu * cd + gf * hprev;
        float av = go * tanhf(cv);

        g_h[t & 1][hc * BBATCH + b] = av;               // coalesced (b contiguous)
        out[(size_t)t * (BBATCH * HD) + b * HD + hc] = av;

        if (t != TS - 1) grid_barrier_128();
    }
}

// ---------------------------------------------------------------------------
extern "C" void kernel_launch(void* const* d_in, const int* in_sizes, int n_in,
                              void* d_out, int out_size)
{
    const float* x   = (const float*)d_in[0];
    const float* a0  = (const float*)d_in[1];
    const float* W   = (const float*)d_in[2];
    const float* U   = (const float*)d_in[3];
    const float* bia = (const float*)d_in[4];
    float* out = (float*)d_out;

    cudaFuncSetAttribute(lstm_scan_kernel,
                         cudaFuncAttributeMaxDynamicSharedMemorySize, SCAN_SMEM);

    gemm_xw_kernel<<<dim3(GD / 128, (TS * BBATCH) / 128), 256>>>(x, W, bia);
    lstm_scan_kernel<<<NBLK, 256, SCAN_SMEM>>>(a0, U, out);
}

// round 2
// speedup vs baseline: 1.3365x; 1.3365x over previous
#include <cuda_runtime.h>
#include <cstdint>

// Problem dims
#define TS 512
#define BB 64
#define ID 512
#define HD 512
#define GD 2048

// Scan config
#define NBLK 128
#define HSS 68                       // padded h row stride (floats), 16B aligned
#define US_FLOATS (512 * 16)         // U tile [k][hl*4+g]
#define HS_FLOATS (512 * HSS)        // h tile [k][b]
#define RED_U64   (3 * 64 * 8)       // k-split reduction buffer
#define SCAN_SMEM ((US_FLOATS + HS_FLOATS) * 4 + RED_U64 * 8)

// Static scratch (no allocation anywhere)
__device__ float g_xw[TS * BB * GD];   // [t][hc][b][gate]
__device__ float g_h[2][HD * BB];      // [hc][b], double buffered
__device__ unsigned g_gen = 0;
__device__ unsigned g_count = 0;

// ---------------- packed fp32x2 helpers (Blackwell 2x fp32) ----------------
static __device__ __forceinline__ uint64_t pack2(float x, float y) {
    uint64_t d; asm("mov.b64 %0,{%1,%2};" : "=l"(d) : "f"(x), "f"(y)); return d;
}
static __device__ __forceinline__ void unpack2(uint64_t d, float& x, float& y) {
    asm("mov.b64 {%0,%1},%2;" : "=f"(x), "=f"(y) : "l"(d));
}
static __device__ __forceinline__ uint64_t ffma2(uint64_t a, uint64_t b, uint64_t c) {
    uint64_t d; asm("fma.rn.f32x2 %0,%1,%2,%3;" : "=l"(d) : "l"(a), "l"(b), "l"(c)); return d;
}
static __device__ __forceinline__ uint64_t fadd2(uint64_t a, uint64_t b) {
    uint64_t d; asm("add.rn.f32x2 %0,%1,%2;" : "=l"(d) : "l"(a), "l"(b)); return d;
}

// ---------------------------------------------------------------------------
// Kernel 1: xW = x @ W + b with packed f32x2 FMA.
// 128x128x8 tile, 256 threads, acc = 8x4 packed pairs. Bias folded into init.
// Output remapped to [t][hc][b][gate] (gate quads contiguous for the scan).
// ---------------------------------------------------------------------------
__global__ void __launch_bounds__(256, 2) gemm_xw_kernel(
    const float* __restrict__ A,     // x  [32768][512]
    const float* __restrict__ Bw,    // W  [512][2048]
    const float* __restrict__ bias)  // [2048]
{
    __shared__ float As[8][128];
    __shared__ float Bs[8][128];

    const int tid = threadIdx.x;
    const int m0 = blockIdx.y * 128;
    const int n0 = blockIdx.x * 128;

    const int a_row = tid >> 1;
    const int a_col = (tid & 1) * 4;
    const int b_row = tid >> 5;
    const int b_col = (tid & 31) * 4;
    const int tx = (tid & 15) * 8;
    const int ty = (tid >> 4) * 8;

    uint64_t acc[8][4];
    {
        float4 bA = *(const float4*)&bias[n0 + tx];
        float4 bB = *(const float4*)&bias[n0 + tx + 4];
        uint64_t b2[4] = { pack2(bA.x, bA.y), pack2(bA.z, bA.w),
                           pack2(bB.x, bB.y), pack2(bB.z, bB.w) };
#pragma unroll
        for (int i = 0; i < 8; i++)
#pragma unroll
            for (int j = 0; j < 4; j++) acc[i][j] = b2[j];
    }

    const float* Aptr = A + (m0 + a_row) * ID + a_col;
    const float* Bptr = Bw + b_row * GD + n0 + b_col;

    for (int k0 = 0; k0 < ID; k0 += 8) {
        float4 av = *(const float4*)(Aptr + k0);
        float4 bv = *(const float4*)(Bptr + (size_t)k0 * GD);
        __syncthreads();
        As[a_col + 0][a_row] = av.x;
        As[a_col + 1][a_row] = av.y;
        As[a_col + 2][a_row] = av.z;
        As[a_col + 3][a_row] = av.w;
        *(float4*)&Bs[b_row][b_col] = bv;
        __syncthreads();
#pragma unroll
        for (int k = 0; k < 8; k++) {
            float4 a0 = *(const float4*)&As[k][ty];
            float4 a1 = *(const float4*)&As[k][ty + 4];
            const uint64_t* bp2 = (const uint64_t*)&Bs[k][tx];
            uint64_t bf0 = bp2[0], bf1 = bp2[1], bf2 = bp2[2], bf3 = bp2[3];
            uint64_t ad[8] = { pack2(a0.x, a0.x), pack2(a0.y, a0.y),
                               pack2(a0.z, a0.z), pack2(a0.w, a0.w),
                               pack2(a1.x, a1.x), pack2(a1.y, a1.y),
                               pack2(a1.z, a1.z), pack2(a1.w, a1.w) };
#pragma unroll
            for (int i = 0; i < 8; i++) {
                acc[i][0] = ffma2(ad[i], bf0, acc[i][0]);
                acc[i][1] = ffma2(ad[i], bf1, acc[i][1]);
                acc[i][2] = ffma2(ad[i], bf2, acc[i][2]);
                acc[i][3] = ffma2(ad[i], bf3, acc[i][3]);
            }
        }
    }

    // store: g_xw[t*131072 + hc*256 + b*4 + gate]
#pragma unroll
    for (int i = 0; i < 8; i++) {
        int m = m0 + ty + i;
        int t = m >> 6;
        int b = m & 63;
        float* base = g_xw + (size_t)t * (BB * GD) + b * 4;
#pragma unroll
        for (int j = 0; j < 4; j++) {
            float lo, hi;
            unpack2(acc[i][j], lo, hi);
            int n = n0 + tx + 2 * j;
            int gate = n >> 9;
            int hc = n & 511;
            base[hc * 256 + gate] = lo;          // n and n+1 share the gate
            base[(hc + 1) * 256 + gate] = hi;
        }
    }
}

// ---------------------------------------------------------------------------
// Software grid barrier (monotonic generation, self-cleaning across replays)
// ---------------------------------------------------------------------------
__device__ __forceinline__ void grid_barrier_128()
{
    __syncthreads();
    if (threadIdx.x == 0) {
        __threadfence();
        volatile unsigned* vgen = &g_gen;
        unsigned gen = *vgen;
        if (atomicAdd(&g_count, 1) == NBLK - 1) {
            atomicExch(&g_count, 0);
            __threadfence();
            atomicAdd(&g_gen, 1);
        } else {
            while (*vgen == gen) { }
        }
        __threadfence();
    }
    __syncthreads();
}

// ---------------------------------------------------------------------------
// Kernel 2: persistent scan. 128 blocks x 256 threads.
// Thread (bp 0..31, hg 0..1, kh 0..3):
//   hidden cols hc0 = bid*4 + hg*2 + {0,1}, batches {2bp, 2bp+1},
//   k-range [kh*128, kh*128+128). 8 packed accumulators per thread.
// Inner k: 1 LDS.64 (h pair) + 2 LDS.128 (u quads, broadcast) + 2 packs
//          + 8 FFMA2 (16 FMAs). k-split partials reduced via smem.
// ---------------------------------------------------------------------------
__global__ void __launch_bounds__(256, 1) lstm_scan_kernel(
    const float* __restrict__ a0,   // [64][512]
    const float* __restrict__ U,    // [512][2048]
    float* __restrict__ out)        // [512][64][512]
{
    extern __shared__ float sm[];
    float* Us = sm;                                   // [512][16] hl-major, gate inner
    float* hs = sm + US_FLOATS;                       // [512][HSS]
    uint64_t* red = (uint64_t*)(sm + US_FLOATS + HS_FLOATS);

    const int tid = threadIdx.x;
    const int bid = blockIdx.x;

    for (int i = tid; i < US_FLOATS; i += 256) {
        int k = i >> 4, c = i & 15, hl = c >> 2, g = c & 3;
        Us[i] = U[(size_t)k * GD + g * HD + bid * 4 + hl];
    }

    const int bp = tid & 31;
    const int hg = (tid >> 5) & 1;
    const int kh = tid >> 6;               // 0..3
    const int b0 = bp * 2;
    const int hc0 = bid * 4 + hg * 2;

    const float* hp  = hs + (kh * 128) * HSS + b0;
    const float* up0 = Us + (kh * 128) * 16 + hg * 8;
    const float* xwbase = g_xw + hc0 * 256 + b0 * 4;

    for (int t = 0; t < TS; t++) {
        __syncthreads();                   // everyone done with previous hs
        if (t == 0) {
            for (int f = tid; f < BB * HD; f += 256) {
                int bb = f >> 9, kk = f & 511;
                hs[kk * HSS + bb] = a0[f]; // one-time transpose
            }
        } else {
            const float* hsrc = g_h[(t ^ 1) & 1];
#pragma unroll
            for (int i = 0; i < 32; i++) {
                int f = i * 1024 + tid * 4;
                float4 v = *(const float4*)(hsrc + f);
                int kk = f >> 6, bb = f & 63;
                *(float4*)&hs[kk * HSS + bb] = v;
            }
        }
        __syncthreads();

        // A[hl2][gatepair][batch]
        uint64_t A000, A001, A010, A011, A100, A101, A110, A111;
        if (kh == 0) {
            const float* xwt = xwbase + (size_t)t * (BB * GD);
            float4 x00 = *(const float4*)(xwt);         // hc0,   b0 : g0..g3
            float4 x01 = *(const float4*)(xwt + 4);     // hc0,   b1
            float4 x10 = *(const float4*)(xwt + 256);   // hc0+1, b0
            float4 x11 = *(const float4*)(xwt + 260);   // hc0+1, b1
            A000 = pack2(x00.x, x00.y); A010 = pack2(x00.z, x00.w);
            A001 = pack2(x01.x, x01.y); A011 = pack2(x01.z, x01.w);
            A100 = pack2(x10.x, x10.y); A110 = pack2(x10.z, x10.w);
            A101 = pack2(x11.x, x11.y); A111 = pack2(x11.z, x11.w);
        } else {
            A000 = A001 = A010 = A011 = A100 = A101 = A110 = A111 = 0ULL;
        }

#pragma unroll 4
        for (int k = 0; k < 128; k++) {
            float2 hv = *(const float2*)(hp + k * HSS);
            const uint64_t* up = (const uint64_t*)(up0 + k * 16);
            uint64_t u0a = up[0], u0b = up[1], u1a = up[2], u1b = up[3];
            uint64_t h0 = pack2(hv.x, hv.x);
            uint64_t h1 = pack2(hv.y, hv.y);
            A000 = ffma2(u0a, h0, A000);
            A010 = ffma2(u0b, h0, A010);
            A001 = ffma2(u0a, h1, A001);
            A011 = ffma2(u0b, h1, A011);
            A100 = ffma2(u1a, h0, A100);
            A110 = ffma2(u1b, h0, A110);
            A101 = ffma2(u1a, h1, A101);
            A111 = ffma2(u1b, h1, A111);
        }

        // reduce the 4 k-splits
        if (kh != 0) {
            uint64_t* rp = red + (size_t)((kh - 1) * 64 + (tid & 63)) * 8;
            rp[0] = A000; rp[1] = A001; rp[2] = A010; rp[3] = A011;
            rp[4] = A100; rp[5] = A101; rp[6] = A110; rp[7] = A111;
        }
        __syncthreads();
        if (kh == 0) {
#pragma unroll
            for (int p = 0; p < 3; p++) {
                const uint64_t* q = red + (size_t)(p * 64 + tid) * 8;
                A000 = fadd2(A000, q[0]); A001 = fadd2(A001, q[1]);
                A010 = fadd2(A010, q[2]); A011 = fadd2(A011, q[3]);
                A100 = fadd2(A100, q[4]); A101 = fadd2(A101, q[5]);
                A110 = fadd2(A110, q[6]); A111 = fadd2(A111, q[7]);
            }

            float h00 = hs[hc0 * HSS + b0],       h01 = hs[hc0 * HSS + b0 + 1];
            float h10 = hs[(hc0 + 1) * HSS + b0], h11 = hs[(hc0 + 1) * HSS + b0 + 1];

            float av[4];
            uint64_t P01[4] = { A000, A001, A100, A101 };
            uint64_t P23[4] = { A010, A011, A110, A111 };
            float hpv[4] = { h00, h01, h10, h11 };
#pragma unroll
            for (int o = 0; o < 4; o++) {
                float xu, xf, xo, xc;
                unpack2(P01[o], xu, xf);
                unpack2(P23[o], xo, xc);
                float su = 1.f / (1.f + __expf(-xu));
                float sf = 1.f / (1.f + __expf(-xf));
                float so = 1.f / (1.f + __expf(-xo));
                float cd = tanhf(xc);
                float cv = su * cd + sf * hpv[o];
                av[o] = so * tanhf(cv);
            }

            float* ht = g_h[t & 1];
            *(float2*)&ht[hc0 * BB + b0]       = make_float2(av[0], av[1]);
            *(float2*)&ht[(hc0 + 1) * BB + b0] = make_float2(av[2], av[3]);

            float* ot = out + (size_t)t * (BB * HD);
            ot[b0 * HD + hc0]           = av[0];
            ot[(b0 + 1) * HD + hc0]     = av[1];
            ot[b0 * HD + hc0 + 1]       = av[2];
            ot[(b0 + 1) * HD + hc0 + 1] = av[3];
        }

        if (t != TS - 1) grid_barrier_128();
    }
}

// ---------------------------------------------------------------------------
extern "C" void kernel_launch(void* const* d_in, const int* in_sizes, int n_in,
                              void* d_out, int out_size)
{
    const float* x   = (const float*)d_in[0];
    const float* a0  = (const float*)d_in[1];
    const float* W   = (const float*)d_in[2];
    const float* U   = (const float*)d_in[3];
    const float* bia = (const float*)d_in[4];
    float* out = (float*)d_out;

    cudaFuncSetAttribute(lstm_scan_kernel,
                         cudaFuncAttributeMaxDynamicSharedMemorySize, SCAN_SMEM);

    gemm_xw_kernel<<<dim3(GD / 128, (TS * BB) / 128), 256>>>(x, W, bia);
    lstm_scan_kernel<<<NBLK, 256, SCAN_SMEM>>>(a0, U, out);
}